// round 12
// baseline (speedup 1.0000x reference)
#include <cuda_runtime.h>
#include <math.h>
#include <cstdint>

// ---------------------------------------------------------------------------
// SimplifiedIFEBranch — R12: persistent kernel (128 CTAs x 512 thr) with ALL
// bulk movement via cp.async.bulk (TMA): W tiles staged in phase0 under one
// mbarrier, A slices bulk-copied per fc phase. Inner loops: LDS + FFMA2 only.
// Activations pair-packed (u64) end-to-end.
// ---------------------------------------------------------------------------

#define NCTA 128
#define W1_OFF 0            // 32 x 768 = 24576 f (96 KB)
#define W2_OFF 24576        // 16 x 256 =  4096 f (16 KB)
#define W3_OFF 28672        //  2 x 512 =  1024 f ( 4 KB)
#define A_OFF  29696        // A region / hist bins / scratch (96 KB)
#define SMEM_FLOATS 54272
#define SMEM_BYTES  (SMEM_FLOATS * 4)   // 217088 B

typedef unsigned long long ull;

__device__ __forceinline__ float c_LO() { return (float)(-3.2 - (6.4 / 256.0) / 2.0); }
__device__ __forceinline__ float c_HI() { return (float)( 3.2 - (6.4 / 256.0) / 2.0); }
__device__ __forceinline__ float c_BW() {
    return (float)(((3.2 - (6.4 / 256.0) / 2.0) - (-3.2 - (6.4 / 256.0) / 2.0)) / 32.0);
}

// Scratch (__device__ globals; no allocation allowed). All pair-packed:
// buffer[(k>>1)*64 + b*2 + (k&1)]
__device__ float g_histP[3072 * 32];
__device__ float g_x1P[1024 * 32];
__device__ float g_x2P[512 * 32];
__device__ unsigned int g_bar_count = 0;
__device__ unsigned int g_bar_gen   = 0;

// ---- packed f32x2 helpers -----------------------------------------------------
__device__ __forceinline__ ull pack2(float x, float y) {
    ull r; asm("mov.b64 %0, {%1, %2};" : "=l"(r) : "f"(x), "f"(y)); return r;
}
__device__ __forceinline__ void ffma2(ull& d, ull a, ull b) {
    asm("fma.rn.f32x2 %0, %1, %2, %0;" : "+l"(d) : "l"(a), "l"(b));
}
__device__ __forceinline__ float unpack_sum(ull p) {
    float lo, hi; asm("mov.b64 {%0, %1}, %2;" : "=f"(lo), "=f"(hi) : "l"(p));
    return lo + hi;
}
__device__ __forceinline__ ull relu_pack(ull p) {
    float lo, hi; asm("mov.b64 {%0, %1}, %2;" : "=f"(lo), "=f"(hi) : "l"(p));
    return pack2(fmaxf(lo, 0.0f), fmaxf(hi, 0.0f));
}

// ---- mbarrier + bulk-copy helpers ------------------------------------------------
__device__ __forceinline__ unsigned smem_u32(const void* p) {
    return (unsigned)__cvta_generic_to_shared(p);
}
__device__ __forceinline__ void mbar_init(unsigned addr, unsigned count) {
    asm volatile("mbarrier.init.shared::cta.b64 [%0], %1;" :: "r"(addr), "r"(count) : "memory");
}
__device__ __forceinline__ void mbar_expect(unsigned addr, unsigned bytes) {
    asm volatile("mbarrier.arrive.expect_tx.shared::cta.b64 _, [%0], %1;"
                 :: "r"(addr), "r"(bytes) : "memory");
}
__device__ __forceinline__ void bulk_g2s(unsigned dst, const void* src,
                                         unsigned bytes, unsigned mbar) {
    asm volatile("cp.async.bulk.shared::cta.global.mbarrier::complete_tx::bytes "
                 "[%0], [%1], %2, [%3];"
                 :: "r"(dst), "l"(src), "r"(bytes), "r"(mbar) : "memory");
}
__device__ __forceinline__ void mbar_wait(unsigned addr) {
    asm volatile(
        "{\n\t.reg .pred P1;\n"
        "WAIT_%=:\n\t"
        "mbarrier.try_wait.parity.acquire.cta.shared::cta.b64 P1, [%0], 0, 0x989680;\n\t"
        "@P1 bra.uni DONE_%=;\n\t"
        "bra.uni WAIT_%=;\n"
        "DONE_%=:\n\t}"
        :: "r"(addr) : "memory");
}

// ---- software grid barrier ----------------------------------------------------------
__device__ __forceinline__ void grid_barrier() {
    __syncthreads();
    if (threadIdx.x == 0) {
        unsigned gen = *(volatile unsigned*)&g_bar_gen;
        __threadfence();
        unsigned old = atomicAdd(&g_bar_count, 1u);
        if (old == NCTA - 1) {
            g_bar_count = 0;
            __threadfence();
            atomicAdd(&g_bar_gen, 1u);
        } else {
            while (*(volatile unsigned*)&g_bar_gen == gen) { __nanosleep(32); }
        }
        __threadfence();
    }
    __syncthreads();
}

// ---- histogram helper ------------------------------------------------------------------
__device__ __forceinline__ void hist_add(float* h, float Iu, float Iv, float w) {
    const float LO = c_LO(), HI = c_HI(), BW = c_BW();
    if (Iu >= LO && Iu <= HI && Iv >= LO && Iv <= HI) {
        int iu = (int)floorf((Iu - LO) / BW);
        int iv = (int)floorf((Iv - LO) / BW);
        iu = min(max(iu, 0), 31);
        iv = min(max(iv, 0), 31);
        atomicAdd(&h[iu * 32 + iv], w);
    }
}

// ---- the one kernel -----------------------------------------------------------------------
__global__ __launch_bounds__(512, 1) void fused_kernel(
    const float* __restrict__ img,
    const float* __restrict__ W1, const float* __restrict__ b1,
    const float* __restrict__ W2, const float* __restrict__ b2,
    const float* __restrict__ W3, const float* __restrict__ b3,
    float* __restrict__ out,
    float* __restrict__ histP, float* __restrict__ x1P, float* __restrict__ x2P) {

    extern __shared__ float buf[];
    __shared__ ull mbars[4];
    __shared__ float ssum[3];

    const int cta  = blockIdx.x;
    const int tid  = threadIdx.x;
    const int lane = tid & 31;
    const int w    = tid >> 5;

    const unsigned mb0 = smem_u32(&mbars[0]);
    const unsigned mb1 = smem_u32(&mbars[1]);
    const unsigned mb2 = smem_u32(&mbars[2]);
    const unsigned mb3 = smem_u32(&mbars[3]);
    const unsigned sA  = smem_u32(buf + A_OFF);

    if (tid == 0) {
        mbar_init(mb0, 1); mbar_init(mb1, 1); mbar_init(mb2, 1); mbar_init(mb3, 1);
    }
    __syncthreads();

    // ---- early pixel loads (hist CTAs) so DRAM latency overlaps staging ----
    float r0 = 0, g0 = 0, l0 = 0, r1 = 0, g1 = 0, l1 = 0;
    if (cta < 32) {
        const float* base = img + (size_t)cta * 3 * 262144;
        const int p0 = tid, p1 = tid + 512;
        const int off0 = ((p0 >> 5) * 16) * 512 + ((p0 & 31) * 16);
        const int off1 = ((p1 >> 5) * 16) * 512 + ((p1 & 31) * 16);
        r0 = __ldcg(base + off0);
        g0 = __ldcg(base + 262144 + off0);
        l0 = __ldcg(base + 524288 + off0);
        r1 = __ldcg(base + off1);
        g1 = __ldcg(base + 262144 + off1);
        l1 = __ldcg(base + 524288 + off1);
    }

    // ---- Phase 0: bulk-stage ALL W tiles (one mbarrier, DMA-serviced) ----
    if (tid == 0) {
        mbar_expect(mb0, 98304u + 16384u + 4096u);
        const float* w1s = W1 + (size_t)((cta & 31) * 32) * 3072 + (cta >> 5) * 768;
        #pragma unroll 4
        for (int r = 0; r < 32; ++r)
            bulk_g2s(smem_u32(buf + W1_OFF + r * 768), w1s + (size_t)r * 3072, 3072u, mb0);
        const float* w2s = W2 + (size_t)((cta & 31) * 16) * 1024 + (cta >> 5) * 256;
        #pragma unroll 4
        for (int r = 0; r < 16; ++r)
            bulk_g2s(smem_u32(buf + W2_OFF + r * 256), w2s + (size_t)r * 1024, 1024u, mb0);
        bulk_g2s(smem_u32(buf + W3_OFF), W3 + (size_t)cta * 2 * 512, 4096u, mb0);
    }

    // ---- bias pre-init (pair-packed accumulators) ----
    {
        const int idx = cta * 512 + tid;
        if (idx < 32768) {
            const int n = idx >> 5, b = idx & 31;
            __stcg(&x1P[(n >> 1) * 64 + b * 2 + (n & 1)], __ldcg(b1 + n));
        } else if (idx < 49152) {
            const int j = idx - 32768, n = j >> 5, b = j & 31;
            __stcg(&x2P[(n >> 1) * 64 + b * 2 + (n & 1)], __ldcg(b2 + n));
        }
    }

    // ---- histogram (CTAs 0..31) using A region as bins ----
    if (cta < 32) {
        float* sh = buf + A_OFF;
        #pragma unroll
        for (int i = tid; i < 3072; i += 512) sh[i] = 0.0f;
        if (tid < 3) ssum[tid] = 0.0f;
        __syncthreads();

        if (r0 > 0.0f && g0 > 0.0f && l0 > 0.0f) {
            float wgt = sqrtf(r0 * r0 + g0 * g0 + l0 * l0);
            float lr = logf(r0), lg = logf(g0), lb = logf(l0);
            hist_add(&sh[0],    lr - lb, lr - lg, wgt);
            hist_add(&sh[1024], lg - lb, lg - lr, wgt);
            hist_add(&sh[2048], lb - lg, lb - lr, wgt);
        }
        if (r1 > 0.0f && g1 > 0.0f && l1 > 0.0f) {
            float wgt = sqrtf(r1 * r1 + g1 * g1 + l1 * l1);
            float lr = logf(r1), lg = logf(g1), lb = logf(l1);
            hist_add(&sh[0],    lr - lb, lr - lg, wgt);
            hist_add(&sh[1024], lg - lb, lg - lr, wgt);
            hist_add(&sh[2048], lb - lg, lb - lr, wgt);
        }
        __syncthreads();

        #pragma unroll
        for (int c = 0; c < 3; ++c) {
            float s = sh[c * 1024 + tid] + sh[c * 1024 + tid + 512];
            #pragma unroll
            for (int o = 16; o > 0; o >>= 1) s += __shfl_down_sync(0xffffffffu, s, o);
            if ((tid & 31) == 0) atomicAdd(&ssum[c], s);
        }
        __syncthreads();

        #pragma unroll
        for (int i = tid; i < 1024; i += 512) {
            #pragma unroll
            for (int c = 0; c < 3; ++c) {
                const int k = c * 1024 + i;
                float v = sqrtf(sh[c * 1024 + i] / ssum[c]);
                __stcg(&histP[(k >> 1) * 64 + cta * 2 + (k & 1)], v);
            }
        }
    }

    mbar_wait(mb0);           // W tiles resident
    grid_barrier();           // histP + bias-preinit visible everywhere

    // =========== fc1: 1024 x 3072 — nb=cta&31 (32 n), kb=cta>>5 (768 K) ==========
    if (tid == 0) {
        mbar_expect(mb1, 98304u);
        const float* a1 = histP + (size_t)(cta >> 5) * 768 * 32;
        #pragma unroll 4
        for (int r = 0; r < 32; ++r)
            bulk_g2s(sA + r * 3072u, a1 + (size_t)r * 768, 3072u, mb1);
    }
    mbar_wait(mb1);
    {
        const int kg = w >> 1, ng = w & 1;        // KG=8 x NG=2, CH=96, NT=16
        const ull* As = reinterpret_cast<const ull*>(buf + A_OFF) + (size_t)(kg * 48) * 32 + lane;
        const float* Ws = buf + W1_OFF + (size_t)(ng * 16) * 768 + kg * 96;

        ull acc[16];
        #pragma unroll
        for (int t = 0; t < 16; ++t) acc[t] = 0ull;

        #pragma unroll 4
        for (int k4 = 0; k4 < 24; ++k4) {
            ull a0 = As[(2 * k4) * 32];
            ull a1 = As[(2 * k4 + 1) * 32];
            #pragma unroll
            for (int t = 0; t < 16; ++t) {
                ulonglong2 wv = *reinterpret_cast<const ulonglong2*>(Ws + (size_t)t * 768 + 4 * k4);
                ffma2(acc[t], wv.x, a0);
                ffma2(acc[t], wv.y, a1);
            }
        }
        __syncthreads();
        float* scr = buf + A_OFF;
        #pragma unroll
        for (int t = 0; t < 16; ++t) scr[(w * 16 + t) * 32 + lane] = unpack_sum(acc[t]);
        __syncthreads();

        #pragma unroll
        for (int n = w; n < 32; n += 16) {
            const int nng = n >> 4, tt = n & 15;
            float s = 0.0f;
            #pragma unroll
            for (int kk = 0; kk < 8; ++kk)
                s += scr[((kk * 2 + nng) * 16 + tt) * 32 + lane];
            const int nn = (cta & 31) * 32 + n;
            atomicAdd(&x1P[(nn >> 1) * 64 + lane * 2 + (nn & 1)], s);
        }
        __syncthreads();
    }
    grid_barrier();

    // =========== fc2: 512 x 1024 — nb=cta&31 (16 n), kb=cta>>5 (256 K) ===========
    if (tid == 0) {
        mbar_expect(mb2, 32768u);
        const float* a2 = x1P + (size_t)(cta >> 5) * 256 * 32;
        #pragma unroll
        for (int r = 0; r < 8; ++r)
            bulk_g2s(sA + r * 4096u, a2 + (size_t)r * 1024, 4096u, mb2);
    }
    mbar_wait(mb2);
    {
        const int kg = w >> 1, ng = w & 1;        // KG=8 x NG=2, CH=32, NT=8
        const ull* As = reinterpret_cast<const ull*>(buf + A_OFF) + (size_t)(kg * 16) * 32 + lane;
        const float* Ws = buf + W2_OFF + (size_t)(ng * 8) * 256 + kg * 32;

        ull acc[8];
        #pragma unroll
        for (int t = 0; t < 8; ++t) acc[t] = 0ull;

        #pragma unroll
        for (int k4 = 0; k4 < 8; ++k4) {
            ull a0 = relu_pack(As[(2 * k4) * 32]);
            ull a1 = relu_pack(As[(2 * k4 + 1) * 32]);
            #pragma unroll
            for (int t = 0; t < 8; ++t) {
                ulonglong2 wv = *reinterpret_cast<const ulonglong2*>(Ws + (size_t)t * 256 + 4 * k4);
                ffma2(acc[t], wv.x, a0);
                ffma2(acc[t], wv.y, a1);
            }
        }
        __syncthreads();
        float* scr = buf + A_OFF;
        #pragma unroll
        for (int t = 0; t < 8; ++t) scr[(w * 8 + t) * 32 + lane] = unpack_sum(acc[t]);
        __syncthreads();

        if (w < 16) {
            const int n = w, nng = n >> 3, tt = n & 7;
            float s = 0.0f;
            #pragma unroll
            for (int kk = 0; kk < 8; ++kk)
                s += scr[((kk * 2 + nng) * 8 + tt) * 32 + lane];
            const int nn = (cta & 31) * 16 + n;
            atomicAdd(&x2P[(nn >> 1) * 64 + lane * 2 + (nn & 1)], s);
        }
        __syncthreads();
    }
    grid_barrier();

    // =========== fc3: 256 x 512 — n0=cta*2, full K=512 ============================
    if (tid == 0) {
        mbar_expect(mb3, 65536u);
        #pragma unroll
        for (int r = 0; r < 16; ++r)
            bulk_g2s(sA + r * 4096u, x2P + (size_t)r * 1024, 4096u, mb3);
    }
    mbar_wait(mb3);
    {
        // 16 warps = KG=16 k-groups, CH=32, NT=2
        const ull* As = reinterpret_cast<const ull*>(buf + A_OFF) + (size_t)(w * 16) * 32 + lane;
        const float* Ws = buf + W3_OFF + w * 32;

        ull acc[2] = {0ull, 0ull};
        #pragma unroll
        for (int k4 = 0; k4 < 8; ++k4) {
            ull a0 = relu_pack(As[(2 * k4) * 32]);
            ull a1 = relu_pack(As[(2 * k4 + 1) * 32]);
            #pragma unroll
            for (int t = 0; t < 2; ++t) {
                ulonglong2 wv = *reinterpret_cast<const ulonglong2*>(Ws + (size_t)t * 512 + 4 * k4);
                ffma2(acc[t], wv.x, a0);
                ffma2(acc[t], wv.y, a1);
            }
        }
        __syncthreads();
        float* scr = buf + A_OFF;
        #pragma unroll
        for (int t = 0; t < 2; ++t) scr[(w * 2 + t) * 32 + lane] = unpack_sum(acc[t]);
        __syncthreads();

        if (w < 2) {
            float s = 0.0f;
            #pragma unroll
            for (int kk = 0; kk < 16; ++kk)
                s += scr[(kk * 2 + w) * 32 + lane];
            s += __ldcg(b3 + cta * 2 + w);
            s = fmaxf(s, 0.0f);
            out[(size_t)lane * 256 + cta * 2 + w] = s;
        }
    }
}

extern "C" void kernel_launch(void* const* d_in, const int* in_sizes, int n_in,
                              void* d_out, int out_size) {
    const float* inp = (const float*)d_in[0];
    const float* W1  = (const float*)d_in[1];
    const float* b1  = (const float*)d_in[2];
    const float* W2  = (const float*)d_in[3];
    const float* b2  = (const float*)d_in[4];
    const float* W3  = (const float*)d_in[5];
    const float* b3  = (const float*)d_in[6];
    float* out = (float*)d_out;

    float* histP; cudaGetSymbolAddress((void**)&histP, g_histP);
    float* x1P;   cudaGetSymbolAddress((void**)&x1P,   g_x1P);
    float* x2P;   cudaGetSymbolAddress((void**)&x2P,   g_x2P);

    cudaFuncSetAttribute(fused_kernel,
                         cudaFuncAttributeMaxDynamicSharedMemorySize, SMEM_BYTES);
    fused_kernel<<<NCTA, 512, SMEM_BYTES>>>(inp, W1, b1, W2, b2, W3, b3, out,
                                            histP, x1P, x2P);
}